// round 9
// baseline (speedup 1.0000x reference)
#include <cuda_runtime.h>
#include <cstdint>
#include <cstddef>

#define N_CTX 4096
#define D_MODEL 2048

// Scratch: X = E@qk, S = scores/probs, Y = P@E
__device__ float g_X[(size_t)N_CTX * D_MODEL];
__device__ float g_S[(size_t)N_CTX * N_CTX];
__device__ float g_Y[(size_t)N_CTX * D_MODEL];

__device__ __forceinline__ float tf32_rn(float x) {
    uint32_t u;
    asm("cvt.rna.tf32.f32 %0, %1;" : "=r"(u) : "f"(x));
    return __uint_as_float(u);
}

// m16n8k8 tf32 MMA, fp32 accumulate (base PTX)
__device__ __forceinline__ void mma8(float c[4], const uint32_t a[4], const uint32_t b[2]) {
    asm volatile(
        "mma.sync.aligned.m16n8k8.row.col.f32.tf32.tf32.f32 "
        "{%0,%1,%2,%3}, {%4,%5,%6,%7}, {%8,%9}, {%0,%1,%2,%3};"
        : "+f"(c[0]), "+f"(c[1]), "+f"(c[2]), "+f"(c[3])
        : "r"(a[0]), "r"(a[1]), "r"(a[2]), "r"(a[3]), "r"(b[0]), "r"(b[1]));
}

// ---------------------------------------------------------------------------
// tf32x3 warp-MMA GEMM: C[M,N] = A[M,K] * op(B), 128x128 CTA, 512 threads.
// STATIC smem, single buffer (R6 structure — fastest so far), but fragments
// stored as interleaved {hi,lo} float2 (stride 40) -> LDS.64 frag loads,
// conflict-free per 16-thread phase. NN-path B unchanged ([16][136] x2).
// ---------------------------------------------------------------------------
template<bool B_TRANS, bool CAUSAL_OUT, bool CAUSAL_K>
__global__ void __launch_bounds__(512, 1)
mma_gemm(const float* __restrict__ A, const float* __restrict__ B,
         float* __restrict__ C, int N, int K)
{
    constexpr int BK = 16;
    __shared__ float As[128 * 40];                  // {h,l} interleaved
    __shared__ float Bs[128 * 40];                  // TN: interleaved; NN: Bh/Bl [16][136]

    const int tid  = threadIdx.x;
    const int wid  = tid >> 5;
    const int lane = tid & 31;
    const int g    = lane >> 2;      // 0..7
    const int tig  = lane & 3;       // 0..3
    const int warpM = wid & 3;
    const int warpN = wid >> 2;

    const int rowBase = blockIdx.y * 128;
    const int colBase = blockIdx.x * 128;

    if (CAUSAL_OUT && colBase > rowBase + 127) {
        const float4 z = make_float4(0.f, 0.f, 0.f, 0.f);
        for (int i = tid; i < 128 * 32; i += 512) {
            int r = i >> 5, c = (i & 31) << 2;
            *reinterpret_cast<float4*>(&C[(size_t)(rowBase + r) * N + colBase + c]) = z;
        }
        return;
    }

    const int numTiles = CAUSAL_K ? (rowBase + 128) / BK : (K / BK);

    const int arow = tid >> 2;          // 0..127
    const int aq   = tid & 3;           // 0..3
    const int bkr  = tid >> 5;          // 0..15 (NN)
    const int bnq  = tid & 31;          // 0..31 (NN)

    float4 va, vb;
    auto gload = [&](int t) {
        const int kBase = t * BK;
        va = *reinterpret_cast<const float4*>(&A[(size_t)(rowBase + arow) * K + kBase + aq * 4]);
        if (B_TRANS)
            vb = *reinterpret_cast<const float4*>(&B[(size_t)(colBase + arow) * K + kBase + aq * 4]);
        else
            vb = *reinterpret_cast<const float4*>(&B[(size_t)(kBase + bkr) * N + colBase + bnq * 4]);
    };

    auto sstore = [&]() {
        float h0 = tf32_rn(va.x), h1 = tf32_rn(va.y), h2 = tf32_rn(va.z), h3 = tf32_rn(va.w);
        float* ap = As + arow * 40 + 8 * aq;
        *reinterpret_cast<float2*>(ap + 0) = make_float2(h0, tf32_rn(va.x - h0));
        *reinterpret_cast<float2*>(ap + 2) = make_float2(h1, tf32_rn(va.y - h1));
        *reinterpret_cast<float2*>(ap + 4) = make_float2(h2, tf32_rn(va.z - h2));
        *reinterpret_cast<float2*>(ap + 6) = make_float2(h3, tf32_rn(va.w - h3));
        float b0 = tf32_rn(vb.x), b1 = tf32_rn(vb.y), b2 = tf32_rn(vb.z), b3 = tf32_rn(vb.w);
        if (B_TRANS) {
            float* bp = Bs + arow * 40 + 8 * aq;
            *reinterpret_cast<float2*>(bp + 0) = make_float2(b0, tf32_rn(vb.x - b0));
            *reinterpret_cast<float2*>(bp + 2) = make_float2(b1, tf32_rn(vb.y - b1));
            *reinterpret_cast<float2*>(bp + 4) = make_float2(b2, tf32_rn(vb.z - b2));
            *reinterpret_cast<float2*>(bp + 6) = make_float2(b3, tf32_rn(vb.w - b3));
        } else {
            float* bh = Bs + bkr * 136 + 4 * bnq;
            float* bl = bh + 16 * 136;
            *reinterpret_cast<float4*>(bh) = make_float4(b0, b1, b2, b3);
            *reinterpret_cast<float4*>(bl) = make_float4(
                tf32_rn(vb.x - b0), tf32_rn(vb.y - b1), tf32_rn(vb.z - b2), tf32_rn(vb.w - b3));
        }
    };

    float acc[2][4][4];
    #pragma unroll
    for (int i = 0; i < 2; ++i)
        #pragma unroll
        for (int j = 0; j < 4; ++j)
            #pragma unroll
            for (int r = 0; r < 4; ++r) acc[i][j][r] = 0.f;

    // hoisted per-warp fragment bases
    const float* const aBase0 = As + (warpM * 32 + g) * 40 + 2 * tig;        // i=0
    const float* const aBase1 = aBase0 + 16 * 40;                            // i=1
    const float* const bBaseT = Bs + (warpN * 32 + g) * 40 + 2 * tig;        // TN, j stride 8*40
    const float* const bBaseN = Bs + tig * 136 + warpN * 32 + g;             // NN, k0 stride 8*136

    gload(0);
    for (int t = 0; t < numTiles; ++t) {
        sstore();
        __syncthreads();
        if (t + 1 < numTiles) gload(t + 1);

        #pragma unroll
        for (int k0 = 0; k0 < BK; k0 += 8) {
            uint32_t ah[2][4], al[2][4], bh[4][2], bl[4][2];
            #pragma unroll
            for (int i = 0; i < 2; ++i) {
                const float* ab = (i ? aBase1 : aBase0) + 2 * k0;
                float2 p0 = *reinterpret_cast<const float2*>(ab);
                float2 p1 = *reinterpret_cast<const float2*>(ab + 320);
                float2 p2 = *reinterpret_cast<const float2*>(ab + 8);
                float2 p3 = *reinterpret_cast<const float2*>(ab + 328);
                ah[i][0] = __float_as_uint(p0.x); al[i][0] = __float_as_uint(p0.y);
                ah[i][1] = __float_as_uint(p1.x); al[i][1] = __float_as_uint(p1.y);
                ah[i][2] = __float_as_uint(p2.x); al[i][2] = __float_as_uint(p2.y);
                ah[i][3] = __float_as_uint(p3.x); al[i][3] = __float_as_uint(p3.y);
            }
            #pragma unroll
            for (int j = 0; j < 4; ++j) {
                if (B_TRANS) {
                    const float* bb = bBaseT + j * 320 + 2 * k0;
                    float2 q0 = *reinterpret_cast<const float2*>(bb);
                    float2 q1 = *reinterpret_cast<const float2*>(bb + 8);
                    bh[j][0] = __float_as_uint(q0.x); bl[j][0] = __float_as_uint(q0.y);
                    bh[j][1] = __float_as_uint(q1.x); bl[j][1] = __float_as_uint(q1.y);
                } else {
                    const float* bp = bBaseN + k0 * 136 + j * 8;
                    bh[j][0] = __float_as_uint(bp[0]);
                    bh[j][1] = __float_as_uint(bp[4 * 136]);
                    bl[j][0] = __float_as_uint(bp[16 * 136]);
                    bl[j][1] = __float_as_uint(bp[16 * 136 + 4 * 136]);
                }
            }
            #pragma unroll
            for (int i = 0; i < 2; ++i)
                #pragma unroll
                for (int j = 0; j < 4; ++j) {
                    mma8(acc[i][j], ah[i], bh[j]);
                    mma8(acc[i][j], ah[i], bl[j]);
                    mma8(acc[i][j], al[i], bh[j]);
                }
        }
        __syncthreads();
    }

    // epilogue
    #pragma unroll
    for (int i = 0; i < 2; ++i) {
        const int gr0 = rowBase + warpM * 32 + i * 16 + g;
        #pragma unroll
        for (int j = 0; j < 4; ++j) {
            const int gc = colBase + warpN * 32 + j * 8 + tig * 2;
            float2 v0 = make_float2(acc[i][j][0], acc[i][j][1]);
            float2 v1 = make_float2(acc[i][j][2], acc[i][j][3]);
            if (CAUSAL_OUT) {
                if (gc + 0 > gr0) v0.x = 0.f;
                if (gc + 1 > gr0) v0.y = 0.f;
                if (gc + 0 > gr0 + 8) v1.x = 0.f;
                if (gc + 1 > gr0 + 8) v1.y = 0.f;
            }
            *reinterpret_cast<float2*>(&C[(size_t)gr0 * N + gc]) = v0;
            *reinterpret_cast<float2*>(&C[(size_t)(gr0 + 8) * N + gc]) = v1;
        }
    }
}

// ---------------------------------------------------------------------------
// In-place causal row softmax (row i uses cols [0,i]; cols > i remain 0).
// ---------------------------------------------------------------------------
__global__ void __launch_bounds__(256)
softmax_rows(float* __restrict__ S)
{
    __shared__ float red[256];
    const int i = blockIdx.x;
    const int len = i + 1;
    float* row = S + (size_t)i * N_CTX;
    const int tid = threadIdx.x;

    float m = -1e30f;
    for (int j = tid; j < len; j += 256) m = fmaxf(m, row[j]);
    red[tid] = m;
    __syncthreads();
    #pragma unroll
    for (int s = 128; s > 0; s >>= 1) {
        if (tid < s) red[tid] = fmaxf(red[tid], red[tid + s]);
        __syncthreads();
    }
    m = red[0];
    __syncthreads();

    float ev[16];
    int cnt = 0;
    float sum = 0.f;
    for (int j = tid; j < len; j += 256) {
        float e = __expf(row[j] - m);
        ev[cnt++] = e;
        sum += e;
    }
    red[tid] = sum;
    __syncthreads();
    #pragma unroll
    for (int s = 128; s > 0; s >>= 1) {
        if (tid < s) red[tid] += red[tid + s];
        __syncthreads();
    }
    const float inv = 1.0f / red[0];

    cnt = 0;
    for (int j = tid; j < len; j += 256) row[j] = ev[cnt++] * inv;
}

// ---------------------------------------------------------------------------
extern "C" void kernel_launch(void* const* d_in, const int* in_sizes, int n_in,
                              void* d_out, int out_size)
{
    const float* E  = (const float*)d_in[0];   // [4096, 2048]
    const float* qk = (const float*)d_in[1];   // [2048, 2048]
    const float* ov = (const float*)d_in[2];   // [2048, 2048]
    float* out = (float*)d_out;                // [4096, 2048]

    void *pX, *pS, *pY;
    cudaGetSymbolAddress(&pX, g_X);
    cudaGetSymbolAddress(&pS, g_S);
    cudaGetSymbolAddress(&pY, g_Y);
    float* X = (float*)pX;
    float* S = (float*)pS;
    float* Y = (float*)pY;

    dim3 blk(512);

    // K1: X = E @ qk        (NN path)
    mma_gemm<false, false, false><<<dim3(D_MODEL / 128, N_CTX / 128), blk>>>(
        E, qk, X, D_MODEL, D_MODEL);

    // K2: S = X @ E^T       (TN path), causal epilogue
    mma_gemm<true, true, false><<<dim3(N_CTX / 128, N_CTX / 128), blk>>>(
        X, E, S, N_CTX, D_MODEL);

    // K3: causal softmax
    softmax_rows<<<N_CTX, dim3(256)>>>(S);

    // K4: Y = P @ E         (NN path; causal K-chunk skip)
    mma_gemm<false, false, true><<<dim3(D_MODEL / 128, N_CTX / 128), blk>>>(
        S, E, Y, D_MODEL, N_CTX);

    // K5: out = Y @ ov      (NN path)
    mma_gemm<false, false, false><<<dim3(D_MODEL / 128, N_CTX / 128), blk>>>(
        Y, ov, out, D_MODEL, D_MODEL);
}

// round 13
// speedup vs baseline: 1.2795x; 1.2795x over previous
#include <cuda_runtime.h>
#include <cstdint>
#include <cstddef>

#define N_CTX 4096
#define D_MODEL 2048

// Scratch: X = E@qk, S = scores/probs, Y = P@E
__device__ float g_X[(size_t)N_CTX * D_MODEL];
__device__ float g_S[(size_t)N_CTX * N_CTX];
__device__ float g_Y[(size_t)N_CTX * D_MODEL];

__device__ __forceinline__ float tf32_rn(float x) {
    uint32_t u;
    asm("cvt.rna.tf32.f32 %0, %1;" : "=r"(u) : "f"(x));
    return __uint_as_float(u);
}

// m16n8k8 tf32 MMA, fp32 accumulate (base PTX)
__device__ __forceinline__ void mma8(float c[4], const uint32_t a[4], const uint32_t b[2]) {
    asm volatile(
        "mma.sync.aligned.m16n8k8.row.col.f32.tf32.tf32.f32 "
        "{%0,%1,%2,%3}, {%4,%5,%6,%7}, {%8,%9}, {%0,%1,%2,%3};"
        : "+f"(c[0]), "+f"(c[1]), "+f"(c[2]), "+f"(c[3])
        : "r"(a[0]), "r"(a[1]), "r"(a[2]), "r"(a[3]), "r"(b[0]), "r"(b[1]));
}

// ---------------------------------------------------------------------------
// tf32 split warp-MMA GEMM: C[M,N] = A[M,K] * op(B), 128x128 CTA, 512 thr.
// EXACT R6 structure (best measured): separate h/l smem arrays stride 20,
// scalar fragment LDS, single buffer, register prefetch of next global tile.
//   TERMS=3: D += Ah*Bh + Ah*Bl + Al*Bh   (pre-softmax accuracy)
//   TERMS=2: D += Ah*Bh + Ah*Bl           (A rounded to tf32; post-softmax)
// ---------------------------------------------------------------------------
template<bool B_TRANS, bool CAUSAL_OUT, bool CAUSAL_K, int TERMS>
__global__ void __launch_bounds__(512, 1)
mma_gemm(const float* __restrict__ A, const float* __restrict__ B,
         float* __restrict__ C, int N, int K)
{
    constexpr int BK = 16;
    __shared__ float As_h[128 * 20], As_l[128 * 20];
    __shared__ float Bs_h[128 * 20], Bs_l[128 * 20];   // NN path uses 16*136

    const int tid  = threadIdx.x;
    const int wid  = tid >> 5;
    const int lane = tid & 31;
    const int g    = lane >> 2;      // 0..7
    const int tig  = lane & 3;       // 0..3
    const int warpM = wid & 3;       // 4 along M
    const int warpN = wid >> 2;      // 4 along N

    const int rowBase = blockIdx.y * 128;
    const int colBase = blockIdx.x * 128;

    if (CAUSAL_OUT && colBase > rowBase + 127) {
        const float4 z = make_float4(0.f, 0.f, 0.f, 0.f);
        for (int i = tid; i < 128 * 32; i += 512) {
            int r = i >> 5, c = (i & 31) << 2;
            *reinterpret_cast<float4*>(&C[(size_t)(rowBase + r) * N + colBase + c]) = z;
        }
        return;
    }

    const int numTiles = CAUSAL_K ? (rowBase + 128) / BK : (K / BK);

    const int arow = tid >> 2;          // 0..127
    const int aq   = tid & 3;           // 0..3
    const int bkr  = tid >> 5;          // 0..15 (NN)
    const int bnq  = tid & 31;          // 0..31 (NN)

    float4 va, vb;
    auto gload = [&](int t) {
        const int kBase = t * BK;
        va = *reinterpret_cast<const float4*>(&A[(size_t)(rowBase + arow) * K + kBase + aq * 4]);
        if (B_TRANS)
            vb = *reinterpret_cast<const float4*>(&B[(size_t)(colBase + arow) * K + kBase + aq * 4]);
        else
            vb = *reinterpret_cast<const float4*>(&B[(size_t)(kBase + bkr) * N + colBase + bnq * 4]);
    };

    auto sstore = [&]() {
        float hx = tf32_rn(va.x), hy = tf32_rn(va.y), hz = tf32_rn(va.z), hw = tf32_rn(va.w);
        int ao = arow * 20 + aq * 4;
        *reinterpret_cast<float4*>(&As_h[ao]) = make_float4(hx, hy, hz, hw);
        if (TERMS == 3) {
            *reinterpret_cast<float4*>(&As_l[ao]) = make_float4(
                tf32_rn(va.x - hx), tf32_rn(va.y - hy), tf32_rn(va.z - hz), tf32_rn(va.w - hw));
        }
        float bx = tf32_rn(vb.x), by = tf32_rn(vb.y), bz = tf32_rn(vb.z), bw = tf32_rn(vb.w);
        float lx = tf32_rn(vb.x - bx), ly = tf32_rn(vb.y - by),
              lz = tf32_rn(vb.z - bz), lw = tf32_rn(vb.w - bw);
        if (B_TRANS) {
            *reinterpret_cast<float4*>(&Bs_h[ao]) = make_float4(bx, by, bz, bw);
            *reinterpret_cast<float4*>(&Bs_l[ao]) = make_float4(lx, ly, lz, lw);
        } else {
            int bo = bkr * 136 + bnq * 4;
            *reinterpret_cast<float4*>(&Bs_h[bo]) = make_float4(bx, by, bz, bw);
            *reinterpret_cast<float4*>(&Bs_l[bo]) = make_float4(lx, ly, lz, lw);
        }
    };

    float acc[2][4][4];
    #pragma unroll
    for (int i = 0; i < 2; ++i)
        #pragma unroll
        for (int j = 0; j < 4; ++j)
            #pragma unroll
            for (int r = 0; r < 4; ++r) acc[i][j][r] = 0.f;

    gload(0);
    for (int t = 0; t < numTiles; ++t) {
        sstore();
        __syncthreads();
        if (t + 1 < numTiles) gload(t + 1);

        #pragma unroll
        for (int k0 = 0; k0 < BK; k0 += 8) {
            uint32_t ah[2][4], al[2][4], bh[4][2], bl[4][2];
            #pragma unroll
            for (int i = 0; i < 2; ++i) {
                int base = (warpM * 32 + i * 16 + g) * 20 + k0 + tig;
                ah[i][0] = __float_as_uint(As_h[base]);
                ah[i][1] = __float_as_uint(As_h[base + 160]);
                ah[i][2] = __float_as_uint(As_h[base + 4]);
                ah[i][3] = __float_as_uint(As_h[base + 164]);
                if (TERMS == 3) {
                    al[i][0] = __float_as_uint(As_l[base]);
                    al[i][1] = __float_as_uint(As_l[base + 160]);
                    al[i][2] = __float_as_uint(As_l[base + 4]);
                    al[i][3] = __float_as_uint(As_l[base + 164]);
                }
            }
            #pragma unroll
            for (int j = 0; j < 4; ++j) {
                if (B_TRANS) {
                    int base = (warpN * 32 + j * 8 + g) * 20 + k0 + tig;
                    bh[j][0] = __float_as_uint(Bs_h[base]);
                    bh[j][1] = __float_as_uint(Bs_h[base + 4]);
                    bl[j][0] = __float_as_uint(Bs_l[base]);
                    bl[j][1] = __float_as_uint(Bs_l[base + 4]);
                } else {
                    int base = (k0 + tig) * 136 + warpN * 32 + j * 8 + g;
                    bh[j][0] = __float_as_uint(Bs_h[base]);
                    bh[j][1] = __float_as_uint(Bs_h[base + 4 * 136]);
                    bl[j][0] = __float_as_uint(Bs_l[base]);
                    bl[j][1] = __float_as_uint(Bs_l[base + 4 * 136]);
                }
            }
            #pragma unroll
            for (int i = 0; i < 2; ++i)
                #pragma unroll
                for (int j = 0; j < 4; ++j) {
                    mma8(acc[i][j], ah[i], bh[j]);
                    mma8(acc[i][j], ah[i], bl[j]);
                    if (TERMS == 3) mma8(acc[i][j], al[i], bh[j]);
                }
        }
        __syncthreads();
    }

    // epilogue
    #pragma unroll
    for (int i = 0; i < 2; ++i) {
        const int gr0 = rowBase + warpM * 32 + i * 16 + g;
        #pragma unroll
        for (int j = 0; j < 4; ++j) {
            const int gc = colBase + warpN * 32 + j * 8 + tig * 2;
            float2 v0 = make_float2(acc[i][j][0], acc[i][j][1]);
            float2 v1 = make_float2(acc[i][j][2], acc[i][j][3]);
            if (CAUSAL_OUT) {
                if (gc + 0 > gr0) v0.x = 0.f;
                if (gc + 1 > gr0) v0.y = 0.f;
                if (gc + 0 > gr0 + 8) v1.x = 0.f;
                if (gc + 1 > gr0 + 8) v1.y = 0.f;
            }
            *reinterpret_cast<float2*>(&C[(size_t)gr0 * N + gc]) = v0;
            *reinterpret_cast<float2*>(&C[(size_t)(gr0 + 8) * N + gc]) = v1;
        }
    }
}

// ---------------------------------------------------------------------------
// In-place causal row softmax (row i uses cols [0,i]; cols > i remain 0).
// ---------------------------------------------------------------------------
__global__ void __launch_bounds__(256)
softmax_rows(float* __restrict__ S)
{
    __shared__ float red[256];
    const int i = blockIdx.x;
    const int len = i + 1;
    float* row = S + (size_t)i * N_CTX;
    const int tid = threadIdx.x;

    float m = -1e30f;
    for (int j = tid; j < len; j += 256) m = fmaxf(m, row[j]);
    red[tid] = m;
    __syncthreads();
    #pragma unroll
    for (int s = 128; s > 0; s >>= 1) {
        if (tid < s) red[tid] = fmaxf(red[tid], red[tid + s]);
        __syncthreads();
    }
    m = red[0];
    __syncthreads();

    float ev[16];
    int cnt = 0;
    float sum = 0.f;
    for (int j = tid; j < len; j += 256) {
        float e = __expf(row[j] - m);
        ev[cnt++] = e;
        sum += e;
    }
    red[tid] = sum;
    __syncthreads();
    #pragma unroll
    for (int s = 128; s > 0; s >>= 1) {
        if (tid < s) red[tid] += red[tid + s];
        __syncthreads();
    }
    const float inv = 1.0f / red[0];

    cnt = 0;
    for (int j = tid; j < len; j += 256) row[j] = ev[cnt++] * inv;
}

// ---------------------------------------------------------------------------
extern "C" void kernel_launch(void* const* d_in, const int* in_sizes, int n_in,
                              void* d_out, int out_size)
{
    const float* E  = (const float*)d_in[0];   // [4096, 2048]
    const float* qk = (const float*)d_in[1];   // [2048, 2048]
    const float* ov = (const float*)d_in[2];   // [2048, 2048]
    float* out = (float*)d_out;                // [4096, 2048]

    void *pX, *pS, *pY;
    cudaGetSymbolAddress(&pX, g_X);
    cudaGetSymbolAddress(&pS, g_S);
    cudaGetSymbolAddress(&pY, g_Y);
    float* X = (float*)pX;
    float* S = (float*)pS;
    float* Y = (float*)pY;

    dim3 blk(512);

    // K1: X = E @ qk        (NN, 3-term: feeds scores)
    mma_gemm<false, false, false, 3><<<dim3(D_MODEL / 128, N_CTX / 128), blk>>>(
        E, qk, X, D_MODEL, D_MODEL);

    // K2: S = X @ E^T       (TN, 3-term), causal epilogue
    mma_gemm<true, true, false, 3><<<dim3(N_CTX / 128, N_CTX / 128), blk>>>(
        X, E, S, N_CTX, D_MODEL);

    // K3: causal softmax
    softmax_rows<<<N_CTX, dim3(256)>>>(S);

    // K4: Y = P @ E         (NN, 2-term: P rounded to tf32; causal K skip)
    mma_gemm<false, false, true, 2><<<dim3(D_MODEL / 128, N_CTX / 128), blk>>>(
        S, E, Y, D_MODEL, N_CTX);

    // K5: out = Y @ ov      (NN, 2-term: Y rounded to tf32)
    mma_gemm<false, false, false, 2><<<dim3(D_MODEL / 128, N_CTX / 128), blk>>>(
        Y, ov, out, D_MODEL, D_MODEL);
}